// round 5
// baseline (speedup 1.0000x reference)
#include <cuda_runtime.h>

#define DIM 128
#define N 512
#define HEADS 4
#define DH 32
#define HID 128
#define IND 5
#define NPAIR 15
#define KSPLIT 4
#define ATTN_SCALE 0.17677669529663687f   // 32^-0.5

// Scratch (allocation-free rule: __device__ globals). 256B-aligned (float4 access).
__device__ __align__(256) float g_qkv[3 * HID * N];     // [384][512] q|k|v
__device__ __align__(256) float g_A2[HEADS * IND * N];  // [h][c][i]
__device__ __align__(256) float g_B3[HEADS * IND * N];  // [h][c][j]
__device__ __align__(256) float g_S4[HEADS * NPAIR];    // packed symmetric quad coeffs
__device__ __align__(256) float g_qk[HEADS * N * N];    // [h][i][j]: qk, then probs (in-place)
__device__ __align__(256) float g_avp[KSPLIT * HID * N];// partial attn@v

__device__ __constant__ int PRC[NPAIR] = {0,0,0,0,0,1,1,1,1,2,2,2,3,3,4};
__device__ __constant__ int PRP[NPAIR] = {0,1,2,3,4,1,2,3,4,2,3,4,3,4,4};

// ---------------------------------------------------------------------------
// K1: tiled GEMM qkv = w_qkv (384x128) @ x (128x512). TM=32,TN=64,TK=16.
// ---------------------------------------------------------------------------
__global__ __launch_bounds__(256) void k_qkv(const float* __restrict__ A,
                                             const float* __restrict__ B,
                                             float* __restrict__ C) {
    __shared__ float As[16][32];
    __shared__ float Bs[16][64];
    const int n0 = blockIdx.x * 64;
    const int m0 = blockIdx.y * 32;
    const int t  = threadIdx.x;
    const int tx = t & 15, ty = t >> 4;

    float acc[2][4] = {};
    for (int k0 = 0; k0 < DIM; k0 += 16) {
#pragma unroll
        for (int idx = t; idx < 512; idx += 256) {
            int kk = idx & 15, m = idx >> 4;
            As[kk][m] = A[(m0 + m) * DIM + k0 + kk];
        }
#pragma unroll
        for (int idx = t; idx < 1024; idx += 256) {
            int n = idx & 63, kk = idx >> 6;
            Bs[kk][n] = B[(k0 + kk) * N + n0 + n];
        }
        __syncthreads();
#pragma unroll
        for (int kk = 0; kk < 16; kk++) {
            float2 a = ((const float2*)&As[kk][0])[ty];
            float4 b = ((const float4*)&Bs[kk][0])[tx];
            acc[0][0] = fmaf(a.x, b.x, acc[0][0]);
            acc[0][1] = fmaf(a.x, b.y, acc[0][1]);
            acc[0][2] = fmaf(a.x, b.z, acc[0][2]);
            acc[0][3] = fmaf(a.x, b.w, acc[0][3]);
            acc[1][0] = fmaf(a.y, b.x, acc[1][0]);
            acc[1][1] = fmaf(a.y, b.y, acc[1][1]);
            acc[1][2] = fmaf(a.y, b.z, acc[1][2]);
            acc[1][3] = fmaf(a.y, b.w, acc[1][3]);
        }
        __syncthreads();
    }
#pragma unroll
    for (int r = 0; r < 2; r++) {
        int m = m0 + ty * 2 + r;
        float* cp = &C[m * N + n0 + tx * 4];
        cp[0] = acc[r][0]; cp[1] = acc[r][1]; cp[2] = acc[r][2]; cp[3] = acc[r][3];
    }
}

// ---------------------------------------------------------------------------
// K2: A2/B3 (coalesced over i) + packed symmetric S4. grid 41, block 512.
// ---------------------------------------------------------------------------
__global__ __launch_bounds__(512) void k_ab(const float* __restrict__ w_ind) {
    const int b = blockIdx.x;
    const int t = threadIdx.x;
    if (b == 40) {
        if (t < HEADS * NPAIR) {
            int h = t / NPAIR, u = t % NPAIR;
            int c = PRC[u], cp = PRP[u];
            float acc = 0.f;
#pragma unroll
            for (int d = 0; d < DH; d++) {
                float wq_c  = w_ind[(h * DH + d) * IND + c];
                float wk_cp = w_ind[(HID + h * DH + d) * IND + cp];
                acc = fmaf(wq_c, wk_cp, acc);
                if (c != cp) {
                    float wq_cp = w_ind[(h * DH + d) * IND + cp];
                    float wk_c  = w_ind[(HID + h * DH + d) * IND + c];
                    acc = fmaf(wq_cp, wk_c, acc);
                }
            }
            g_S4[t] = acc;
        }
        return;
    }
    const bool isA = b < 20;
    const int u = isA ? b : b - 20;
    const int h = u / 5, c = u % 5;
    __shared__ float ws[DH];
    if (t < DH)
        ws[t] = isA ? w_ind[(HID + h * DH + t) * IND + c]   // A2: q . wk_ind
                    : w_ind[(h * DH + t) * IND + c];        // B3: k . wq_ind
    __syncthreads();
    const float* src = g_qkv + (isA ? (h * DH) * N : (HID + h * DH) * N);
    float acc = 0.f;
#pragma unroll
    for (int d = 0; d < DH; d++)
        acc = fmaf(src[d * N + t], ws[d], acc);
    (isA ? g_A2 : g_B3)[(h * IND + c) * N + t] = acc;
}

// ---------------------------------------------------------------------------
// K3: g_qk[h][i][j] = sum_d q[h,d,i]*k[h,d,j].  64x64 tile, 4x4 rtile.
// ---------------------------------------------------------------------------
__global__ __launch_bounds__(256) void k_qk() {
    __shared__ float qs[DH][64];
    __shared__ float ks[DH][64];
    const int j0 = blockIdx.x * 64;
    const int i0 = blockIdx.y * 64;
    const int h  = blockIdx.z;
    const int t  = threadIdx.x;
    const int tx = t & 15, ty = t >> 4;

    const float* qb = g_qkv + (h * DH) * N;
    const float* kb = g_qkv + (HID + h * DH) * N;
#pragma unroll
    for (int idx = t; idx < DH * 64; idx += 256) {
        int d = idx >> 6, c = idx & 63;
        qs[d][c] = qb[d * N + i0 + c];
        ks[d][c] = kb[d * N + j0 + c];
    }
    __syncthreads();

    float acc[4][4] = {};
#pragma unroll
    for (int d = 0; d < DH; d++) {
        float4 qa = ((const float4*)&qs[d][0])[ty];
        float4 kv = ((const float4*)&ks[d][0])[tx];
        acc[0][0] = fmaf(qa.x, kv.x, acc[0][0]);
        acc[0][1] = fmaf(qa.x, kv.y, acc[0][1]);
        acc[0][2] = fmaf(qa.x, kv.z, acc[0][2]);
        acc[0][3] = fmaf(qa.x, kv.w, acc[0][3]);
        acc[1][0] = fmaf(qa.y, kv.x, acc[1][0]);
        acc[1][1] = fmaf(qa.y, kv.y, acc[1][1]);
        acc[1][2] = fmaf(qa.y, kv.z, acc[1][2]);
        acc[1][3] = fmaf(qa.y, kv.w, acc[1][3]);
        acc[2][0] = fmaf(qa.z, kv.x, acc[2][0]);
        acc[2][1] = fmaf(qa.z, kv.y, acc[2][1]);
        acc[2][2] = fmaf(qa.z, kv.z, acc[2][2]);
        acc[2][3] = fmaf(qa.z, kv.w, acc[2][3]);
        acc[3][0] = fmaf(qa.w, kv.x, acc[3][0]);
        acc[3][1] = fmaf(qa.w, kv.y, acc[3][1]);
        acc[3][2] = fmaf(qa.w, kv.z, acc[3][2]);
        acc[3][3] = fmaf(qa.w, kv.w, acc[3][3]);
    }
    float* cb = g_qk + ((size_t)h * N) * N;
#pragma unroll
    for (int r = 0; r < 4; r++) {
        int i = i0 + ty * 4 + r;
        ((float4*)&cb[(size_t)i * N + j0])[tx] =
            make_float4(acc[r][0], acc[r][1], acc[r][2], acc[r][3]);
    }
}

// ---------------------------------------------------------------------------
// K4: sim + softmax for ALL 4 heads, one block per i, float4 per thread.
// 128 threads; writes normalized probs in place over g_qk (LDG/STG.128).
// ---------------------------------------------------------------------------
__global__ __launch_bounds__(128) void k_sim(const float* __restrict__ indicator) {
    const int i = blockIdx.x;
    const int t = threadIdx.x;           // owns j = 4t..4t+3
    const int warp = t >> 5, lane = t & 31;

    __shared__ float a2s[HEADS][IND];
    __shared__ float s4s[HEADS][NPAIR];
    __shared__ float red[HEADS][4];

    if (t < HEADS * IND)
        a2s[t / IND][t % IND] = g_A2[t * N + i];
    else if (t < HEADS * IND + HEADS * NPAIR) {
        int u = t - HEADS * IND;
        s4s[u / NPAIR][u % NPAIR] = g_S4[u];
    }
    __syncthreads();

    // indicator float4 loads (once for all heads)
    float4 iv[IND];
#pragma unroll
    for (int c = 0; c < IND; c++)
        iv[c] = *(const float4*)(indicator + ((size_t)c * N + i) * N + 4 * t);

    // linear term: lin[h] = sum_c iv_c * (A2[h][c] + B3[h][c][j])
    float4 lin[HEADS] = {};
#pragma unroll
    for (int c = 0; c < IND; c++) {
#pragma unroll
        for (int h = 0; h < HEADS; h++) {
            float4 b3 = *(const float4*)(g_B3 + (h * IND + c) * N + 4 * t);
            float a2 = a2s[h][c];
            lin[h].x = fmaf(iv[c].x, a2 + b3.x, lin[h].x);
            lin[h].y = fmaf(iv[c].y, a2 + b3.y, lin[h].y);
            lin[h].z = fmaf(iv[c].z, a2 + b3.z, lin[h].z);
            lin[h].w = fmaf(iv[c].w, a2 + b3.w, lin[h].w);
        }
    }

    // quadratic term: pair products shared across heads
    float4 quad[HEADS] = {};
#pragma unroll
    for (int u = 0; u < NPAIR; u++) {
        const int c = PRC[u], p = PRP[u];
        float4 pp;
        pp.x = iv[c].x * iv[p].x;
        pp.y = iv[c].y * iv[p].y;
        pp.z = iv[c].z * iv[p].z;
        pp.w = iv[c].w * iv[p].w;
#pragma unroll
        for (int h = 0; h < HEADS; h++) {
            float s = s4s[h][u];
            quad[h].x = fmaf(s, pp.x, quad[h].x);
            quad[h].y = fmaf(s, pp.y, quad[h].y);
            quad[h].z = fmaf(s, pp.z, quad[h].z);
            quad[h].w = fmaf(s, pp.w, quad[h].w);
        }
    }

    float4 sim[HEADS];
#pragma unroll
    for (int h = 0; h < HEADS; h++) {
        float4 qk = *(const float4*)(g_qk + ((size_t)h * N + i) * N + 4 * t);
        sim[h].x = ATTN_SCALE * (qk.x + lin[h].x + quad[h].x);
        sim[h].y = ATTN_SCALE * (qk.y + lin[h].y + quad[h].y);
        sim[h].z = ATTN_SCALE * (qk.z + lin[h].z + quad[h].z);
        sim[h].w = ATTN_SCALE * (qk.w + lin[h].w + quad[h].w);
    }

    // --- max reduce ---
    float m4[HEADS];
#pragma unroll
    for (int h = 0; h < HEADS; h++)
        m4[h] = fmaxf(fmaxf(sim[h].x, sim[h].y), fmaxf(sim[h].z, sim[h].w));
#pragma unroll
    for (int off = 16; off; off >>= 1)
#pragma unroll
        for (int h = 0; h < HEADS; h++)
            m4[h] = fmaxf(m4[h], __shfl_xor_sync(0xffffffffu, m4[h], off));
    if (lane == 0)
#pragma unroll
        for (int h = 0; h < HEADS; h++) red[h][warp] = m4[h];
    __syncthreads();
    float gmax[HEADS];
#pragma unroll
    for (int h = 0; h < HEADS; h++)
        gmax[h] = fmaxf(fmaxf(red[h][0], red[h][1]), fmaxf(red[h][2], red[h][3]));
    __syncthreads();

    // --- exp + sum reduce ---
    float4 e[HEADS];
    float s4sum[HEADS];
#pragma unroll
    for (int h = 0; h < HEADS; h++) {
        e[h].x = __expf(sim[h].x - gmax[h]);
        e[h].y = __expf(sim[h].y - gmax[h]);
        e[h].z = __expf(sim[h].z - gmax[h]);
        e[h].w = __expf(sim[h].w - gmax[h]);
        s4sum[h] = (e[h].x + e[h].y) + (e[h].z + e[h].w);
    }
#pragma unroll
    for (int off = 16; off; off >>= 1)
#pragma unroll
        for (int h = 0; h < HEADS; h++)
            s4sum[h] += __shfl_xor_sync(0xffffffffu, s4sum[h], off);
    if (lane == 0)
#pragma unroll
        for (int h = 0; h < HEADS; h++) red[h][warp] = s4sum[h];
    __syncthreads();
#pragma unroll
    for (int h = 0; h < HEADS; h++) {
        float inv = 1.0f / (((red[h][0] + red[h][1]) + (red[h][2] + red[h][3])));
        float4 p;
        p.x = e[h].x * inv; p.y = e[h].y * inv;
        p.z = e[h].z * inv; p.w = e[h].w * inv;
        *(float4*)(g_qk + ((size_t)h * N + i) * N + 4 * t) = p;
    }
}

// ---------------------------------------------------------------------------
// K5: partial attn@v GEMM. out_p[z][h*32+d][i] = sum_{j in split z} P[h,i,j]*v[h,d,j]
// grid (N/64, HEADS, KSPLIT), 128 threads, tile M=32 x N=64, rtile 4x4.
// ---------------------------------------------------------------------------
__global__ __launch_bounds__(128) void k_av() {
    __shared__ float Ps[32][65];   // [kk][n]
    __shared__ float Vs[32][33];   // [kk][m]
    const int i0 = blockIdx.x * 64;
    const int h  = blockIdx.y;
    const int z  = blockIdx.z;
    const int js = z * (N / KSPLIT);
    const int t  = threadIdx.x;
    const int tx = t & 15;         // n quad
    const int ty = t >> 4;         // m quad (0..7)

    const float* P = g_qk + (size_t)h * N * N;
    const float* V = g_qkv + (2 * HID + h * DH) * N;

    float acc[4][4] = {};
    for (int j0 = js; j0 < js + N / KSPLIT; j0 += 32) {
#pragma unroll
        for (int r = 0; r < 16; r++) {          // Ps: 32x64
            int idx = t + r * 128;
            int kk = idx & 31, n = idx >> 5;
            Ps[kk][n] = P[(size_t)(i0 + n) * N + j0 + kk];
        }
#pragma unroll
        for (int r = 0; r < 8; r++) {           // Vs: 32x32
            int idx = t + r * 128;
            int kk = idx & 31, m = idx >> 5;
            Vs[kk][m] = V[m * N + j0 + kk];
        }
        __syncthreads();
#pragma unroll
        for (int kk = 0; kk < 32; kk++) {
            float v0 = Vs[kk][4 * ty + 0], v1 = Vs[kk][4 * ty + 1];
            float v2 = Vs[kk][4 * ty + 2], v3 = Vs[kk][4 * ty + 3];
            float p0 = Ps[kk][4 * tx + 0], p1 = Ps[kk][4 * tx + 1];
            float p2 = Ps[kk][4 * tx + 2], p3 = Ps[kk][4 * tx + 3];
            acc[0][0] = fmaf(v0, p0, acc[0][0]);
            acc[0][1] = fmaf(v0, p1, acc[0][1]);
            acc[0][2] = fmaf(v0, p2, acc[0][2]);
            acc[0][3] = fmaf(v0, p3, acc[0][3]);
            acc[1][0] = fmaf(v1, p0, acc[1][0]);
            acc[1][1] = fmaf(v1, p1, acc[1][1]);
            acc[1][2] = fmaf(v1, p2, acc[1][2]);
            acc[1][3] = fmaf(v1, p3, acc[1][3]);
            acc[2][0] = fmaf(v2, p0, acc[2][0]);
            acc[2][1] = fmaf(v2, p1, acc[2][1]);
            acc[2][2] = fmaf(v2, p2, acc[2][2]);
            acc[2][3] = fmaf(v2, p3, acc[2][3]);
            acc[3][0] = fmaf(v3, p0, acc[3][0]);
            acc[3][1] = fmaf(v3, p1, acc[3][1]);
            acc[3][2] = fmaf(v3, p2, acc[3][2]);
            acc[3][3] = fmaf(v3, p3, acc[3][3]);
        }
        __syncthreads();
    }
    float* outp = g_avp + (size_t)z * HID * N;
#pragma unroll
    for (int r = 0; r < 4; r++) {
        int m = 4 * ty + r;
        float* cp = &outp[(h * DH + m) * N + i0 + 4 * tx];
        cp[0] = acc[r][0]; cp[1] = acc[r][1]; cp[2] = acc[r][2]; cp[3] = acc[r][3];
    }
}

// ---------------------------------------------------------------------------
// K6: out = w_out (128x128) @ (sum_z avp[z]) (128x512) + b_out
// ---------------------------------------------------------------------------
__global__ __launch_bounds__(256) void k_proj(const float* __restrict__ A,
                                              const float* __restrict__ bias,
                                              float* __restrict__ C) {
    __shared__ float As[16][32];
    __shared__ float Bs[16][64];
    const int n0 = blockIdx.x * 64;
    const int m0 = blockIdx.y * 32;
    const int t  = threadIdx.x;
    const int tx = t & 15, ty = t >> 4;

    float acc[2][4] = {};
    for (int k0 = 0; k0 < HID; k0 += 16) {
#pragma unroll
        for (int idx = t; idx < 512; idx += 256) {
            int kk = idx & 15, m = idx >> 4;
            As[kk][m] = A[(m0 + m) * HID + k0 + kk];
        }
#pragma unroll
        for (int idx = t; idx < 1024; idx += 256) {
            int n = idx & 63, kk = idx >> 6;
            float v = 0.f;
#pragma unroll
            for (int zz = 0; zz < KSPLIT; zz++)
                v += g_avp[((size_t)zz * HID + k0 + kk) * N + n0 + n];
            Bs[kk][n] = v;
        }
        __syncthreads();
#pragma unroll
        for (int kk = 0; kk < 16; kk++) {
            float2 a = ((const float2*)&As[kk][0])[ty];
            float4 b = ((const float4*)&Bs[kk][0])[tx];
            acc[0][0] = fmaf(a.x, b.x, acc[0][0]);
            acc[0][1] = fmaf(a.x, b.y, acc[0][1]);
            acc[0][2] = fmaf(a.x, b.z, acc[0][2]);
            acc[0][3] = fmaf(a.x, b.w, acc[0][3]);
            acc[1][0] = fmaf(a.y, b.x, acc[1][0]);
            acc[1][1] = fmaf(a.y, b.y, acc[1][1]);
            acc[1][2] = fmaf(a.y, b.z, acc[1][2]);
            acc[1][3] = fmaf(a.y, b.w, acc[1][3]);
        }
        __syncthreads();
    }
#pragma unroll
    for (int r = 0; r < 2; r++) {
        int m = m0 + ty * 2 + r;
        float bv = bias[m];
        float* cp = &C[m * N + n0 + tx * 4];
        cp[0] = acc[r][0] + bv; cp[1] = acc[r][1] + bv;
        cp[2] = acc[r][2] + bv; cp[3] = acc[r][3] + bv;
    }
}

// ---------------------------------------------------------------------------
extern "C" void kernel_launch(void* const* d_in, const int* in_sizes, int n_in,
                              void* d_out, int out_size) {
    const float* x         = (const float*)d_in[0];   // (1,128,512)
    const float* indicator = (const float*)d_in[1];   // (1,5,512,512)
    const float* w_qkv     = (const float*)d_in[2];   // (384,128)
    const float* w_ind     = (const float*)d_in[3];   // (256,5)
    const float* w_out     = (const float*)d_in[4];   // (128,128)
    const float* b_out     = (const float*)d_in[5];   // (128,)
    float* out             = (float*)d_out;           // (1,128,512)

    float* qkv;  cudaGetSymbolAddress((void**)&qkv, g_qkv);

    k_qkv<<<dim3(8, 12), 256>>>(w_qkv, x, qkv);       // qkv = w_qkv @ x
    k_ab<<<41, 512>>>(w_ind);                          // A2, B3, S4
    k_qk<<<dim3(8, 8, 4), 256>>>();                    // raw q.k
    k_sim<<<N, 128>>>(indicator);                      // sim+softmax -> probs (in place)
    k_av<<<dim3(8, HEADS, KSPLIT), 128>>>();           // partial attn@v
    k_proj<<<dim3(8, 4), 256>>>(w_out, b_out, out);    // w_out @ sum(avp) + b
}

// round 6
// speedup vs baseline: 1.3028x; 1.3028x over previous
#include <cuda_runtime.h>

#define DIM 128
#define N 512
#define HEADS 4
#define DH 32
#define HID 128
#define IND 5
#define KSPLIT 8
#define ATTN_SCALE 0.17677669529663687f   // 32^-0.5

// Scratch (allocation-free rule: __device__ globals). 256B-aligned (vector access).
__device__ __align__(256) float g_qkv[3 * HID * N];     // [384][512] q|k|v
__device__ __align__(256) float g_A2[HEADS * IND * N];  // [h][c][i]
__device__ __align__(256) float g_B3[HEADS * IND * N];  // [h][c][j]
__device__ __align__(256) float g_W4[HEADS * 25];       // [h][c*5+cp]
__device__ __align__(256) float g_qk[HEADS * N * N];    // [h][i][j]: qk, then probs (in-place)
__device__ __align__(256) float g_avp[KSPLIT * HID * N];// partial attn@v

// ---------------------------------------------------------------------------
// K1: tiled GEMM qkv = w_qkv (384x128) @ x (128x512). TM=32,TN=64,TK=16.
// ---------------------------------------------------------------------------
__global__ __launch_bounds__(256) void k_qkv(const float* __restrict__ A,
                                             const float* __restrict__ B,
                                             float* __restrict__ C) {
    __shared__ float As[16][32];
    __shared__ float Bs[16][64];
    const int n0 = blockIdx.x * 64;
    const int m0 = blockIdx.y * 32;
    const int t  = threadIdx.x;
    const int tx = t & 15, ty = t >> 4;

    float acc[2][4] = {};
    for (int k0 = 0; k0 < DIM; k0 += 16) {
#pragma unroll
        for (int idx = t; idx < 512; idx += 256) {
            int kk = idx & 15, m = idx >> 4;
            As[kk][m] = A[(m0 + m) * DIM + k0 + kk];
        }
#pragma unroll
        for (int idx = t; idx < 1024; idx += 256) {
            int n = idx & 63, kk = idx >> 6;
            Bs[kk][n] = B[(k0 + kk) * N + n0 + n];
        }
        __syncthreads();
#pragma unroll
        for (int kk = 0; kk < 16; kk++) {
            float2 a = ((const float2*)&As[kk][0])[ty];
            float4 b = ((const float4*)&Bs[kk][0])[tx];
            acc[0][0] = fmaf(a.x, b.x, acc[0][0]);
            acc[0][1] = fmaf(a.x, b.y, acc[0][1]);
            acc[0][2] = fmaf(a.x, b.z, acc[0][2]);
            acc[0][3] = fmaf(a.x, b.w, acc[0][3]);
            acc[1][0] = fmaf(a.y, b.x, acc[1][0]);
            acc[1][1] = fmaf(a.y, b.y, acc[1][1]);
            acc[1][2] = fmaf(a.y, b.z, acc[1][2]);
            acc[1][3] = fmaf(a.y, b.w, acc[1][3]);
        }
        __syncthreads();
    }
#pragma unroll
    for (int r = 0; r < 2; r++) {
        int m = m0 + ty * 2 + r;
        float* cp = &C[m * N + n0 + tx * 4];
        cp[0] = acc[r][0]; cp[1] = acc[r][1]; cp[2] = acc[r][2]; cp[3] = acc[r][3];
    }
}

// ---------------------------------------------------------------------------
// K2: qk GEMM (z<4) + A2/B3/W4 side-work (z==4). 256 threads.
// ---------------------------------------------------------------------------
__global__ __launch_bounds__(256) void k_qk(const float* __restrict__ w_ind) {
    const int t = threadIdx.x;

    if (blockIdx.z == 4) {
        const int u = blockIdx.y * 8 + blockIdx.x;   // 0..63
        if (u < 40) {
            const bool isA = u < 20;
            const int v = isA ? u : u - 20;
            const int h = v / 5, c = v % 5;
            __shared__ float ws[DH];
            if (t < DH)
                ws[t] = isA ? w_ind[(HID + h * DH + t) * IND + c]  // A2: q . wk_ind
                            : w_ind[(h * DH + t) * IND + c];       // B3: k . wq_ind
            __syncthreads();
            const float* src = g_qkv + (isA ? (h * DH) * N : (HID + h * DH) * N);
            for (int ii = t; ii < N; ii += 256) {
                float acc = 0.f;
#pragma unroll
                for (int d = 0; d < DH; d++)
                    acc = fmaf(src[d * N + ii], ws[d], acc);
                (isA ? g_A2 : g_B3)[(h * IND + c) * N + ii] = acc;
            }
        } else if (u == 40) {
            if (t < HEADS * 25) {
                int h = t / 25, c = (t % 25) / 5, cp = t % 5;
                float acc = 0.f;
#pragma unroll
                for (int d = 0; d < DH; d++)
                    acc = fmaf(w_ind[(h * DH + d) * IND + c],
                               w_ind[(HID + h * DH + d) * IND + cp], acc);
                g_W4[t] = acc;
            }
        }
        return;
    }

    // ---- qk tile: g_qk[h][i][j] = sum_d q[h,d,i]*k[h,d,j] ----
    __shared__ float qs[DH][64];
    __shared__ float ks[DH][64];
    const int j0 = blockIdx.x * 64;
    const int i0 = blockIdx.y * 64;
    const int h  = blockIdx.z;
    const int tx = t & 15, ty = t >> 4;

    const float* qb = g_qkv + (h * DH) * N;
    const float* kb = g_qkv + (HID + h * DH) * N;
#pragma unroll
    for (int idx = t; idx < DH * 64; idx += 256) {
        int d = idx >> 6, c = idx & 63;
        qs[d][c] = qb[d * N + i0 + c];
        ks[d][c] = kb[d * N + j0 + c];
    }
    __syncthreads();

    float acc[4][4] = {};
#pragma unroll
    for (int d = 0; d < DH; d++) {
        float4 qa = ((const float4*)&qs[d][0])[ty];
        float4 kv = ((const float4*)&ks[d][0])[tx];
        acc[0][0] = fmaf(qa.x, kv.x, acc[0][0]);
        acc[0][1] = fmaf(qa.x, kv.y, acc[0][1]);
        acc[0][2] = fmaf(qa.x, kv.z, acc[0][2]);
        acc[0][3] = fmaf(qa.x, kv.w, acc[0][3]);
        acc[1][0] = fmaf(qa.y, kv.x, acc[1][0]);
        acc[1][1] = fmaf(qa.y, kv.y, acc[1][1]);
        acc[1][2] = fmaf(qa.y, kv.z, acc[1][2]);
        acc[1][3] = fmaf(qa.y, kv.w, acc[1][3]);
        acc[2][0] = fmaf(qa.z, kv.x, acc[2][0]);
        acc[2][1] = fmaf(qa.z, kv.y, acc[2][1]);
        acc[2][2] = fmaf(qa.z, kv.z, acc[2][2]);
        acc[2][3] = fmaf(qa.z, kv.w, acc[2][3]);
        acc[3][0] = fmaf(qa.w, kv.x, acc[3][0]);
        acc[3][1] = fmaf(qa.w, kv.y, acc[3][1]);
        acc[3][2] = fmaf(qa.w, kv.z, acc[3][2]);
        acc[3][3] = fmaf(qa.w, kv.w, acc[3][3]);
    }
    float* cb = g_qk + ((size_t)h * N) * N;
#pragma unroll
    for (int r = 0; r < 4; r++) {
        int i = i0 + ty * 4 + r;
        ((float4*)&cb[(size_t)i * N + j0])[tx] =
            make_float4(acc[r][0], acc[r][1], acc[r][2], acc[r][3]);
    }
}

// ---------------------------------------------------------------------------
// K3: sim + softmax for ALL 4 heads, one block per i, float2 per thread.
// 256 threads (8 warps); probs written in place over g_qk.
// ---------------------------------------------------------------------------
__global__ __launch_bounds__(256) void k_sim(const float* __restrict__ indicator) {
    const int i = blockIdx.x;
    const int t = threadIdx.x;          // owns j = 2t, 2t+1
    const int warp = t >> 5, lane = t & 31;

    __shared__ float a2s[HEADS][IND];
    __shared__ float w4s[HEADS][25];
    __shared__ float red[HEADS][8];

    if (t < HEADS * IND)
        a2s[t / IND][t % IND] = g_A2[t * N + i];
    else if (t < HEADS * IND + HEADS * 25) {
        int u = t - HEADS * IND;
        w4s[u / 25][u % 25] = g_W4[u];
    }
    __syncthreads();

    float2 iv[IND];
#pragma unroll
    for (int c = 0; c < IND; c++)
        iv[c] = *(const float2*)(indicator + ((size_t)c * N + i) * N + 2 * t);

    float2 sim[HEADS];
#pragma unroll
    for (int h = 0; h < HEADS; h++) {
        float2 qk = *(const float2*)(g_qk + ((size_t)h * N + i) * N + 2 * t);
        float linx = 0.f, liny = 0.f, quadx = 0.f, quady = 0.f;
#pragma unroll
        for (int c = 0; c < IND; c++) {
            float2 b3 = *(const float2*)(g_B3 + (h * IND + c) * N + 2 * t);
            float a2 = a2s[h][c];
            linx = fmaf(iv[c].x, a2 + b3.x, linx);
            liny = fmaf(iv[c].y, a2 + b3.y, liny);
            float tx2 = 0.f, ty2 = 0.f;
#pragma unroll
            for (int cp = 0; cp < IND; cp++) {
                float w = w4s[h][c * 5 + cp];
                tx2 = fmaf(w, iv[cp].x, tx2);
                ty2 = fmaf(w, iv[cp].y, ty2);
            }
            quadx = fmaf(iv[c].x, tx2, quadx);
            quady = fmaf(iv[c].y, ty2, quady);
        }
        sim[h].x = ATTN_SCALE * (qk.x + linx + quadx);
        sim[h].y = ATTN_SCALE * (qk.y + liny + quady);
    }

    // --- max reduce ---
    float m4[HEADS];
#pragma unroll
    for (int h = 0; h < HEADS; h++) m4[h] = fmaxf(sim[h].x, sim[h].y);
#pragma unroll
    for (int off = 16; off; off >>= 1)
#pragma unroll
        for (int h = 0; h < HEADS; h++)
            m4[h] = fmaxf(m4[h], __shfl_xor_sync(0xffffffffu, m4[h], off));
    if (lane == 0)
#pragma unroll
        for (int h = 0; h < HEADS; h++) red[h][warp] = m4[h];
    __syncthreads();
    float gmax[HEADS];
#pragma unroll
    for (int h = 0; h < HEADS; h++) {
        float g = red[h][0];
#pragma unroll
        for (int w = 1; w < 8; w++) g = fmaxf(g, red[h][w]);
        gmax[h] = g;
    }
    __syncthreads();

    // --- exp + sum reduce ---
    float2 e[HEADS];
    float ss[HEADS];
#pragma unroll
    for (int h = 0; h < HEADS; h++) {
        e[h].x = __expf(sim[h].x - gmax[h]);
        e[h].y = __expf(sim[h].y - gmax[h]);
        ss[h] = e[h].x + e[h].y;
    }
#pragma unroll
    for (int off = 16; off; off >>= 1)
#pragma unroll
        for (int h = 0; h < HEADS; h++)
            ss[h] += __shfl_xor_sync(0xffffffffu, ss[h], off);
    if (lane == 0)
#pragma unroll
        for (int h = 0; h < HEADS; h++) red[h][warp] = ss[h];
    __syncthreads();
#pragma unroll
    for (int h = 0; h < HEADS; h++) {
        float g = 0.f;
#pragma unroll
        for (int w = 0; w < 8; w++) g += red[h][w];
        float inv = 1.0f / g;
        float2 p;
        p.x = e[h].x * inv; p.y = e[h].y * inv;
        *(float2*)(g_qk + ((size_t)h * N + i) * N + 2 * t) = p;
    }
}

// ---------------------------------------------------------------------------
// K4: partial attn@v GEMM. avp[z][h*32+d][i] = sum_{j in split z} P[h,i,j]*v[h,d,j]
// grid (N/64, HEADS, KSPLIT), 128 threads, tile M=32(d) x N=64(i), rtile 4x4.
// ---------------------------------------------------------------------------
__global__ __launch_bounds__(128) void k_av() {
    __shared__ float Ps[32][65];   // [kk][n]
    __shared__ float Vs[32][33];   // [kk][m]
    const int i0 = blockIdx.x * 64;
    const int h  = blockIdx.y;
    const int z  = blockIdx.z;
    const int js = z * (N / KSPLIT);
    const int t  = threadIdx.x;
    const int tx = t & 15;         // n quad
    const int ty = t >> 4;         // m quad (0..7)

    const float* P = g_qk + (size_t)h * N * N;
    const float* V = g_qkv + (2 * HID + h * DH) * N;

    float acc[4][4] = {};
    for (int j0 = js; j0 < js + N / KSPLIT; j0 += 32) {
#pragma unroll
        for (int r = 0; r < 16; r++) {          // Ps: 32x64
            int idx = t + r * 128;
            int kk = idx & 31, n = idx >> 5;
            Ps[kk][n] = P[(size_t)(i0 + n) * N + j0 + kk];
        }
#pragma unroll
        for (int r = 0; r < 8; r++) {           // Vs: 32x32
            int idx = t + r * 128;
            int kk = idx & 31, m = idx >> 5;
            Vs[kk][m] = V[m * N + j0 + kk];
        }
        __syncthreads();
#pragma unroll
        for (int kk = 0; kk < 32; kk++) {
            float v0 = Vs[kk][4 * ty + 0], v1 = Vs[kk][4 * ty + 1];
            float v2 = Vs[kk][4 * ty + 2], v3 = Vs[kk][4 * ty + 3];
            float p0 = Ps[kk][4 * tx + 0], p1 = Ps[kk][4 * tx + 1];
            float p2 = Ps[kk][4 * tx + 2], p3 = Ps[kk][4 * tx + 3];
            acc[0][0] = fmaf(v0, p0, acc[0][0]);
            acc[0][1] = fmaf(v0, p1, acc[0][1]);
            acc[0][2] = fmaf(v0, p2, acc[0][2]);
            acc[0][3] = fmaf(v0, p3, acc[0][3]);
            acc[1][0] = fmaf(v1, p0, acc[1][0]);
            acc[1][1] = fmaf(v1, p1, acc[1][1]);
            acc[1][2] = fmaf(v1, p2, acc[1][2]);
            acc[1][3] = fmaf(v1, p3, acc[1][3]);
            acc[2][0] = fmaf(v2, p0, acc[2][0]);
            acc[2][1] = fmaf(v2, p1, acc[2][1]);
            acc[2][2] = fmaf(v2, p2, acc[2][2]);
            acc[2][3] = fmaf(v2, p3, acc[2][3]);
            acc[3][0] = fmaf(v3, p0, acc[3][0]);
            acc[3][1] = fmaf(v3, p1, acc[3][1]);
            acc[3][2] = fmaf(v3, p2, acc[3][2]);
            acc[3][3] = fmaf(v3, p3, acc[3][3]);
        }
        __syncthreads();
    }
    float* outp = g_avp + (size_t)z * HID * N;
#pragma unroll
    for (int r = 0; r < 4; r++) {
        int m = 4 * ty + r;
        float* cp = &outp[(h * DH + m) * N + i0 + 4 * tx];
        cp[0] = acc[r][0]; cp[1] = acc[r][1]; cp[2] = acc[r][2]; cp[3] = acc[r][3];
    }
}

// ---------------------------------------------------------------------------
// K5: out = w_out (128x128) @ (sum_z avp[z]) (128x512) + b_out
// ---------------------------------------------------------------------------
__global__ __launch_bounds__(256) void k_proj(const float* __restrict__ A,
                                              const float* __restrict__ bias,
                                              float* __restrict__ C) {
    __shared__ float As[16][32];
    __shared__ float Bs[16][64];
    const int n0 = blockIdx.x * 64;
    const int m0 = blockIdx.y * 32;
    const int t  = threadIdx.x;
    const int tx = t & 15, ty = t >> 4;

    float acc[2][4] = {};
    for (int k0 = 0; k0 < HID; k0 += 16) {
#pragma unroll
        for (int idx = t; idx < 512; idx += 256) {
            int kk = idx & 15, m = idx >> 4;
            As[kk][m] = A[(m0 + m) * HID + k0 + kk];
        }
#pragma unroll
        for (int idx = t; idx < 1024; idx += 256) {
            int n = idx & 63, kk = idx >> 6;
            float v = 0.f;
#pragma unroll
            for (int zz = 0; zz < KSPLIT; zz++)
                v += g_avp[((size_t)zz * HID + k0 + kk) * N + n0 + n];
            Bs[kk][n] = v;
        }
        __syncthreads();
#pragma unroll
        for (int kk = 0; kk < 16; kk++) {
            float2 a = ((const float2*)&As[kk][0])[ty];
            float4 b = ((const float4*)&Bs[kk][0])[tx];
            acc[0][0] = fmaf(a.x, b.x, acc[0][0]);
            acc[0][1] = fmaf(a.x, b.y, acc[0][1]);
            acc[0][2] = fmaf(a.x, b.z, acc[0][2]);
            acc[0][3] = fmaf(a.x, b.w, acc[0][3]);
            acc[1][0] = fmaf(a.y, b.x, acc[1][0]);
            acc[1][1] = fmaf(a.y, b.y, acc[1][1]);
            acc[1][2] = fmaf(a.y, b.z, acc[1][2]);
            acc[1][3] = fmaf(a.y, b.w, acc[1][3]);
        }
        __syncthreads();
    }
#pragma unroll
    for (int r = 0; r < 2; r++) {
        int m = m0 + ty * 2 + r;
        float bv = bias[m];
        float* cp = &C[m * N + n0 + tx * 4];
        cp[0] = acc[r][0] + bv; cp[1] = acc[r][1] + bv;
        cp[2] = acc[r][2] + bv; cp[3] = acc[r][3] + bv;
    }
}

// ---------------------------------------------------------------------------
extern "C" void kernel_launch(void* const* d_in, const int* in_sizes, int n_in,
                              void* d_out, int out_size) {
    const float* x         = (const float*)d_in[0];   // (1,128,512)
    const float* indicator = (const float*)d_in[1];   // (1,5,512,512)
    const float* w_qkv     = (const float*)d_in[2];   // (384,128)
    const float* w_ind     = (const float*)d_in[3];   // (256,5)
    const float* w_out     = (const float*)d_in[4];   // (128,128)
    const float* b_out     = (const float*)d_in[5];   // (128,)
    float* out             = (float*)d_out;           // (1,128,512)

    float* qkv;  cudaGetSymbolAddress((void**)&qkv, g_qkv);

    k_qkv<<<dim3(8, 12), 256>>>(w_qkv, x, qkv);        // qkv = w_qkv @ x
    k_qk<<<dim3(8, 8, 5), 256>>>(w_ind);               // raw q.k  +  A2/B3/W4
    k_sim<<<N, 256>>>(indicator);                      // sim+softmax -> probs (in place)
    k_av<<<dim3(8, HEADS, KSPLIT), 128>>>();           // partial attn@v
    k_proj<<<dim3(8, 4), 256>>>(w_out, b_out, out);    // w_out @ sum(avp) + b
}